// round 6
// baseline (speedup 1.0000x reference)
#include <cuda_runtime.h>
#include <cstddef>

// N=8192, D=2, L=1.0, R0=0.1, no self-loop.
// Output: [0, N*N) dist (f32, row-major), [N*N, 2*N*N) mask as 0.0/1.0.
#define NPTS 8192
#define R0_SQ 0.01f
#define THREADS 256
#define IT 2   // i-rows per thread: j-point loads amortized over 2 rows

__global__ __launch_bounds__(THREADS)
void radius_graph_kernel(const float* __restrict__ x, float* __restrict__ out)
{
    // j fastest in the grid (R5 win: concurrent CTA wave writes contiguous
    // row-bands); i slow, IT rows per block.
    const int j0 = (blockIdx.x * THREADS + threadIdx.x) * 4;
    const int i0 = blockIdx.y * IT;

    // Block-uniform i-points: one 16B broadcast load covers both rows
    const float4 q01 = *reinterpret_cast<const float4*>(x + 2 * i0);
    const float ix[IT] = {q01.x, q01.z};
    const float iy[IT] = {q01.y, q01.w};

    // Per-thread j-points loaded ONCE, reused for both rows (halves L1 load
    // wavefronts per stored byte)
    const float4 p01 = *reinterpret_cast<const float4*>(x + 2 * j0);
    const float4 p23 = *reinterpret_cast<const float4*>(x + 2 * j0 + 4);
    const float px[4] = {p01.x, p01.z, p23.x, p23.z};
    const float py[4] = {p01.y, p01.w, p23.y, p23.w};

#pragma unroll
    for (int m = 0; m < IT; ++m) {
        float4 dist4, mask4;
        float* dp = &dist4.x;
        float* mp = &mask4.x;

#pragma unroll
        for (int k = 0; k < 4; ++k) {
            float dx = px[k] - ix[m];
            float dy = py[k] - iy[m];
            // Periodic minimum-image, L=1: dr -= round(dr) (rintf = half-even,
            // matching jnp.round)
            dx -= rintf(dx);
            dy -= rintf(dy);
            const float d2 = fmaf(dx, dx, dy * dy);
            float d;
            asm("sqrt.approx.f32 %0, %1;" : "=f"(d) : "f"(d2));
            dp[k] = d;
            mp[k] = (d2 < R0_SQ && (j0 + k) != (i0 + m)) ? 1.0f : 0.0f;
        }

        const size_t base = (size_t)(i0 + m) * NPTS + (size_t)j0;
        // Streaming stores: write-only output, evict-first in L2
        __stcs(reinterpret_cast<float4*>(out + base), dist4);
        __stcs(reinterpret_cast<float4*>(out + (size_t)NPTS * NPTS + base), mask4);
    }
}

extern "C" void kernel_launch(void* const* d_in, const int* in_sizes, int n_in,
                              void* d_out, int out_size)
{
    (void)n_in; (void)in_sizes; (void)out_size;
    const float* x = (const float*)d_in[0];
    float* out = (float*)d_out;

    dim3 grid(NPTS / (THREADS * 4), NPTS / IT);  // (8, 4096): j fastest
    radius_graph_kernel<<<grid, THREADS>>>(x, out);
}

// round 7
// speedup vs baseline: 1.0190x; 1.0190x over previous
#include <cuda_runtime.h>
#include <cstddef>

// N=8192, D=2, L=1.0, R0=0.1, no self-loop.
// Output: [0, N*N) dist (f32, row-major), [N*N, 2*N*N) mask as 0.0/1.0.
#define NPTS 8192
#define R0_SQ 0.01f
#define THREADS 256
#define IT 4   // i-rows per thread; combined with j-fastest grid (untested combo)

__global__ __launch_bounds__(THREADS)
void radius_graph_kernel(const float* __restrict__ x, float* __restrict__ out)
{
    // j fastest in the grid (R5 win); i slow, IT rows per block.
    const int j0 = (blockIdx.x * THREADS + threadIdx.x) * 4;
    const int i0 = blockIdx.y * IT;

    // Block-uniform i-points (two 16B broadcast loads cover 4 rows)
    const float4 q01 = *reinterpret_cast<const float4*>(x + 2 * i0);
    const float4 q23 = *reinterpret_cast<const float4*>(x + 2 * i0 + 4);
    const float ix[IT] = {q01.x, q01.z, q23.x, q23.z};
    const float iy[IT] = {q01.y, q01.w, q23.y, q23.w};

    // Per-thread j-points loaded ONCE, reused for all 4 rows
    const float4 p01 = *reinterpret_cast<const float4*>(x + 2 * j0);
    const float4 p23 = *reinterpret_cast<const float4*>(x + 2 * j0 + 4);
    const float px[4] = {p01.x, p01.z, p23.x, p23.z};
    const float py[4] = {p01.y, p01.w, p23.y, p23.w};

#pragma unroll
    for (int m = 0; m < IT; ++m) {
        float4 dist4, mask4;
        float* dp = &dist4.x;
        float* mp = &mask4.x;

#pragma unroll
        for (int k = 0; k < 4; ++k) {
            float dx = px[k] - ix[m];
            float dy = py[k] - iy[m];
            // Periodic minimum-image, L=1: dr -= round(dr) (rintf = half-even,
            // matching jnp.round)
            dx -= rintf(dx);
            dy -= rintf(dy);
            const float d2 = fmaf(dx, dx, dy * dy);
            float d;
            asm("sqrt.approx.f32 %0, %1;" : "=f"(d) : "f"(d2));
            dp[k] = d;
            mp[k] = (d2 < R0_SQ && (j0 + k) != (i0 + m)) ? 1.0f : 0.0f;
        }

        const size_t base = (size_t)(i0 + m) * NPTS + (size_t)j0;
        // Streaming stores: write-only output, evict-first in L2
        __stcs(reinterpret_cast<float4*>(out + base), dist4);
        __stcs(reinterpret_cast<float4*>(out + (size_t)NPTS * NPTS + base), mask4);
    }
}

extern "C" void kernel_launch(void* const* d_in, const int* in_sizes, int n_in,
                              void* d_out, int out_size)
{
    (void)n_in; (void)in_sizes; (void)out_size;
    const float* x = (const float*)d_in[0];
    float* out = (float*)d_out;

    dim3 grid(NPTS / (THREADS * 4), NPTS / IT);  // (8, 2048): j fastest
    radius_graph_kernel<<<grid, THREADS>>>(x, out);
}